// round 2
// baseline (speedup 1.0000x reference)
#include <cuda_runtime.h>
#include <math.h>
#include <math_constants.h>

#define NN    50000
#define EE    800000
#define DIN   128
#define DH    128
#define DOUTC 40

// ---------------- device scratch (no allocs allowed) ----------------
__device__ float g_h [NN*DH];    // h' = (x@W) * dinv[row]
__device__ float g_x1[NN*DH];    // layer output ping
__device__ float g_x2[NN*DH];    // layer output pong
__device__ float g_dinv[NN];
__device__ int   g_deg[NN];
__device__ int   g_rowptr[NN+1];
__device__ int   g_cursor[NN];
__device__ int   g_srcs[EE];     // edge srcs sorted by dst (CSR)

// ---------------- preprocessing: CSR build ----------------
__global__ void zero_deg_k() {
    int i = blockIdx.x*blockDim.x + threadIdx.x;
    if (i < NN) g_deg[i] = 0;
}

// edge_index is int32 (JAX x64 disabled): [0:EE)=src, [EE:2EE)=dst
__global__ void count_deg_k(const int* __restrict__ ei) {
    int e = blockIdx.x*blockDim.x + threadIdx.x;
    if (e < EE) {
        unsigned d = (unsigned)ei[EE + e];
        if (d < NN) atomicAdd(&g_deg[d], 1);
    }
}

// single block: exclusive prefix sum of deg -> rowptr, cursor; dinv = rsqrt(deg+1)
__global__ void scan_k() {
    __shared__ int partial[1024];
    int tid = threadIdx.x;
    const int CH = (NN + 1023) / 1024;   // 49
    int start = tid * CH;
    int s = 0;
    for (int i = 0; i < CH; i++) {
        int idx = start + i;
        if (idx < NN) s += g_deg[idx];
    }
    partial[tid] = s;
    __syncthreads();
    for (int off = 1; off < 1024; off <<= 1) {
        int v = (tid >= off) ? partial[tid - off] : 0;
        __syncthreads();
        partial[tid] += v;
        __syncthreads();
    }
    int base = (tid > 0) ? partial[tid - 1] : 0;
    for (int i = 0; i < CH; i++) {
        int idx = start + i;
        if (idx < NN) {
            int d = g_deg[idx];
            g_rowptr[idx] = base;
            g_cursor[idx] = base;
            g_dinv[idx]   = rsqrtf((float)(d + 1));  // +1 self-loop
            base += d;
        }
    }
    if (tid == 1023) g_rowptr[NN] = partial[1023];
}

__global__ void sort_edges_k(const int* __restrict__ ei) {
    int e = blockIdx.x*blockDim.x + threadIdx.x;
    if (e < EE) {
        unsigned d = (unsigned)ei[EE + e];
        unsigned srec = (unsigned)ei[e];
        if (d < NN && srec < NN) {
            int pos = atomicAdd(&g_cursor[d], 1);
            if (pos < EE) g_srcs[pos] = (int)srec;
        }
    }
}

// ---------------- GEMM: H = (X @ W) * dinv[row] ----------------
// 256 threads/block, 64 rows/block, thread = 8 rows x 4 cols micro-tile.
// SRCSEL: 0 = external ptr, 1 = g_x1, 2 = g_x2. Output always g_h.
template<int NC, int SRCSEL>
__global__ void gemm_scale_k(const float* __restrict__ Xp, const float* __restrict__ W) {
    const float* X = (SRCSEL == 0) ? Xp : (SRCSEL == 1 ? (const float*)g_x1 : (const float*)g_x2);
    float* H = g_h;

    __shared__ float xs[64][DIN];            // 32 KB
    int tid  = threadIdx.x;
    int row0 = blockIdx.x * 64;

    const float4* Xv = (const float4*)(X + (size_t)row0 * DIN);
    float4* xsv = (float4*)&xs[0][0];
    #pragma unroll
    for (int i = 0; i < 8; i++) {
        int idx = tid + i * 256;             // 0..2047 float4
        int r = idx >> 5;                    // 32 float4 per row
        xsv[idx] = (row0 + r < NN) ? Xv[idx] : make_float4(0.f, 0.f, 0.f, 0.f);
    }
    __syncthreads();

    int tx = tid & 31, ty = tid >> 5;
    if (tx * 4 >= NC) return;

    float4 acc[8];
    #pragma unroll
    for (int r = 0; r < 8; r++) acc[r] = make_float4(0.f, 0.f, 0.f, 0.f);

    const float* wp = W + tx * 4;
    int rb = ty * 8;
    #pragma unroll 4
    for (int k = 0; k < DIN; k++) {
        float4 b = *(const float4*)(wp + (size_t)k * NC);
        #pragma unroll
        for (int r = 0; r < 8; r++) {
            float a = xs[rb + r][k];
            acc[r].x = fmaf(a, b.x, acc[r].x);
            acc[r].y = fmaf(a, b.y, acc[r].y);
            acc[r].z = fmaf(a, b.z, acc[r].z);
            acc[r].w = fmaf(a, b.w, acc[r].w);
        }
    }

    #pragma unroll
    for (int r = 0; r < 8; r++) {
        int row = row0 + rb + r;
        if (row < NN) {
            float dv = g_dinv[row];
            float4 o;
            o.x = acc[r].x * dv; o.y = acc[r].y * dv;
            o.z = acc[r].z * dv; o.w = acc[r].w * dv;
            *(float4*)(H + (size_t)row * NC + tx * 4) = o;
        }
    }
}

// ---------------- aggregation: pull-mode CSR reduction ----------------
// one warp per node; Xo[i] = relu( dinv[i]*(sum_{src in N(i)} h'[src] + h'[i]) + b )
// DSTSEL: 1 = g_x1, 2 = g_x2
template<int D, int DSTSEL>
__global__ void aggregate_k(const float* __restrict__ bias) {
    int gw   = (blockIdx.x*blockDim.x + threadIdx.x) >> 5;
    int lane = threadIdx.x & 31;
    if (gw >= NN) return;
    const int NV = D / 4;                  // float4 per row
    if (lane >= NV) return;

    const float4* Hv = (const float4*)(const float*)g_h;
    float* Xo = (DSTSEL == 1) ? (float*)g_x1 : (float*)g_x2;

    float4 acc = Hv[(size_t)gw * NV + lane];   // self-loop contribution h'[i]

    int e   = g_rowptr[gw];
    int end = g_rowptr[gw + 1];
    for (; e + 3 < end; e += 4) {
        int s0 = g_srcs[e], s1 = g_srcs[e+1], s2 = g_srcs[e+2], s3 = g_srcs[e+3];
        float4 v0 = Hv[(size_t)s0 * NV + lane];
        float4 v1 = Hv[(size_t)s1 * NV + lane];
        float4 v2 = Hv[(size_t)s2 * NV + lane];
        float4 v3 = Hv[(size_t)s3 * NV + lane];
        acc.x += (v0.x + v1.x) + (v2.x + v3.x);
        acc.y += (v0.y + v1.y) + (v2.y + v3.y);
        acc.z += (v0.z + v1.z) + (v2.z + v3.z);
        acc.w += (v0.w + v1.w) + (v2.w + v3.w);
    }
    for (; e < end; e++) {
        int s = g_srcs[e];
        float4 v = Hv[(size_t)s * NV + lane];
        acc.x += v.x; acc.y += v.y; acc.z += v.z; acc.w += v.w;
    }

    float dv  = g_dinv[gw];
    float4 bb = ((const float4*)bias)[lane];
    float4 o;
    o.x = fmaxf(fmaf(acc.x, dv, bb.x), 0.f);
    o.y = fmaxf(fmaf(acc.y, dv, bb.y), 0.f);
    o.z = fmaxf(fmaf(acc.z, dv, bb.z), 0.f);
    o.w = fmaxf(fmaf(acc.w, dv, bb.w), 0.f);
    ((float4*)Xo)[(size_t)gw * NV + lane] = o;
}

// ---------------- log_softmax over 40 cols, one warp per row ----------------
__global__ void logsoftmax_k(float* __restrict__ out) {
    int row  = (blockIdx.x*blockDim.x + threadIdx.x) >> 5;
    int lane = threadIdx.x & 31;
    if (row >= NN) return;
    const float* p = (const float*)g_x1 + (size_t)row * DOUTC;
    float v0 = (lane < DOUTC)      ? p[lane]      : -CUDART_INF_F;
    float v1 = (lane + 32 < DOUTC) ? p[lane + 32] : -CUDART_INF_F;
    float m = fmaxf(v0, v1);
    #pragma unroll
    for (int o = 16; o; o >>= 1) m = fmaxf(m, __shfl_xor_sync(0xffffffffu, m, o));
    float s = 0.f;
    if (lane < DOUTC)      s += __expf(v0 - m);
    if (lane + 32 < DOUTC) s += __expf(v1 - m);
    #pragma unroll
    for (int o = 16; o; o >>= 1) s += __shfl_xor_sync(0xffffffffu, s, o);
    float lse = m + __logf(s);
    float* q = out + (size_t)row * DOUTC;
    if (lane < DOUTC)      q[lane]      = v0 - lse;
    if (lane + 32 < DOUTC) q[lane + 32] = v1 - lse;
}

// ---------------- launch ----------------
extern "C" void kernel_launch(void* const* d_in, const int* in_sizes, int n_in,
                              void* d_out, int out_size) {
    const float* x  = (const float*)d_in[0];
    const int*   ei = (const int*)d_in[1];      // int32: JAX x64 disabled
    const float* W0 = (const float*)d_in[2];
    const float* b0 = (const float*)d_in[3];
    const float* W1 = (const float*)d_in[4];
    const float* b1 = (const float*)d_in[5];
    const float* W2 = (const float*)d_in[6];
    const float* b2 = (const float*)d_in[7];
    float* out = (float*)d_out;

    // CSR build (per call; deterministic up to fp-irrelevant within-node order)
    zero_deg_k  <<<(NN + 255)/256, 256>>>();
    count_deg_k <<<(EE + 255)/256, 256>>>(ei);
    scan_k      <<<1, 1024>>>();
    sort_edges_k<<<(EE + 255)/256, 256>>>(ei);

    const int GG = (NN + 63) / 64;          // gemm blocks (64 rows each)
    const int GA = (NN * 32 + 255) / 256;   // one warp per node

    // layer 0: x -> g_h -> g_x1
    gemm_scale_k<128, 0><<<GG, 256>>>(x, W0);
    aggregate_k <128, 1><<<GA, 256>>>(b0);
    // layer 1: g_x1 -> g_h -> g_x2
    gemm_scale_k<128, 1><<<GG, 256>>>(nullptr, W1);
    aggregate_k <128, 2><<<GA, 256>>>(b1);
    // layer 2: g_x2 -> g_h(40) -> g_x1(40)
    gemm_scale_k<40, 2><<<GG, 256>>>(nullptr, W2);
    aggregate_k <40, 1><<<GA, 256>>>(b2);
    // log_softmax -> out
    logsoftmax_k<<<GA, 256>>>(out);
}